// round 15
// baseline (speedup 1.0000x reference)
#include <cuda_runtime.h>
#include <cstdint>

// COO SpMM via direct fixed-capacity row buckets, D = 64.
// R15: hot kernels frozen at R10 (best: 107.9us). Overhead trim only:
//      - g_count zeroed by a cudaMemsetAsync graph node (was a 148-block
//        grid-stride kernel inside tail_cleanup, 4.3us)
//      - overflow handling shrunk to a 1-block kernel that self-resets
//        g_ovf_count (normally 0 -> immediate exit).

#define D_DIM    64
#define N_MAX    100000
#define E_MAX    3200000
#define CAP      128          // slots per row (avg degree 32, P(deg>128)~0)
#define OVF_CAP  8192

__device__ int  g_count[N_MAX];                  // zero-init at load; memset per launch
__device__ int2 g_bucket[(size_t)N_MAX * CAP];   // {col, float bits of val}
__device__ int  g_ovf_count;                     // zero-init; self-reset by ovf kernel
__device__ int4 g_ovf[OVF_CAP];                  // {row, col, valbits, 0}

// ---- Phase 1: bucket scatter (R7/R10 scalar form — at its scattered-op floor) --

__global__ void scatter_bucket(const int* __restrict__ idx,
                               const float* __restrict__ vals, int E) {
    int e = blockIdx.x * blockDim.x + threadIdx.x;
    if (e >= E) return;
    int row = idx[e];
    int col = idx[E + e];
    int vb  = __float_as_int(vals[e]);
    int pos = atomicAdd(&g_count[row], 1);
    if (pos < CAP) {
        g_bucket[(size_t)row * CAP + pos] = make_int2(col, vb);
    } else {
        int o = atomicAdd(&g_ovf_count, 1);
        if (o < OVF_CAP) g_ovf[o] = make_int4(row, col, vb, 0);
    }
}

// ---- Phase 2: one warp per row; int4 bucket loads (exact R10 body) ------------

__global__ void __launch_bounds__(256) spmm_bucket(const float* __restrict__ b,
                                                   float* __restrict__ out, int n) {
    int warp = (blockIdx.x * blockDim.x + threadIdx.x) >> 5;
    int lane = threadIdx.x & 31;
    if (warp >= n) return;

    int cnt = g_count[warp];
    if (cnt > CAP) cnt = CAP;

    const int4* __restrict__ bkt4 =
        reinterpret_cast<const int4*>(g_bucket + (size_t)warp * CAP);
    const float2* __restrict__ B = reinterpret_cast<const float2*>(b);
    float a0 = 0.f, a1 = 0.f;

    int pairs = cnt >> 1;
    #pragma unroll 2
    for (int i = 0; i < pairs; i++) {
        int4  p  = bkt4[i];                   // 2 edges in one broadcast LDG
        float v0 = __int_as_float(p.y);
        float v1 = __int_as_float(p.w);
        float2 b0 = __ldg(&B[(long long)p.x * 32 + lane]);
        float2 b1 = __ldg(&B[(long long)p.z * 32 + lane]);
        a0 = fmaf(v0, b0.x, a0);
        a1 = fmaf(v0, b0.y, a1);
        a0 = fmaf(v1, b1.x, a0);
        a1 = fmaf(v1, b1.y, a1);
    }
    if (cnt & 1) {
        int2  p  = g_bucket[(size_t)warp * CAP + (cnt - 1)];
        float v  = __int_as_float(p.y);
        float2 bv = __ldg(&B[(long long)p.x * 32 + lane]);
        a0 = fmaf(v, bv.x, a0);
        a1 = fmaf(v, bv.y, a1);
    }

    reinterpret_cast<float2*>(out)[(long long)warp * 32 + lane] =
        make_float2(a0, a1);
}

// ---- Phase 3: overflow apply (1 block; normally instant exit) -----------------

__global__ void apply_overflow(const float* __restrict__ b,
                               float* __restrict__ out) {
    int novf = g_ovf_count;
    if (novf == 0) return;                 // the expected path
    if (novf > OVF_CAP) novf = OVF_CAP;

    int t = threadIdx.x;
    for (int s = t; s < novf * 16; s += blockDim.x) {
        int  k = s >> 4;
        int  j = (s & 15) << 2;
        int4 ov = g_ovf[k];
        float v = __int_as_float(ov.z);
        const float4 bv =
            *reinterpret_cast<const float4*>(b + (long long)ov.y * D_DIM + j);
        float* dst = out + (long long)ov.x * D_DIM + j;
        asm volatile("red.global.add.v4.f32 [%0], {%1, %2, %3, %4};"
                     :: "l"(dst), "f"(bv.x * v), "f"(bv.y * v),
                        "f"(bv.z * v), "f"(bv.w * v)
                     : "memory");
    }
    __syncthreads();
    if (t == 0) g_ovf_count = 0;           // self-reset for next replay
}

// ---- Launch --------------------------------------------------------------------

extern "C" void kernel_launch(void* const* d_in, const int* in_sizes, int n_in,
                              void* d_out, int out_size) {
    const int*   idx  = (const int*)d_in[0];          // [2, E]
    const float* vals = (const float*)d_in[1];        // [E]
    const float* b    = (const float*)d_in[n_in - 1]; // [N, 64]
    float*       out  = (float*)d_out;

    int E = in_sizes[1];
    int N = out_size / D_DIM;
    if (E > E_MAX) E = E_MAX;
    if (N > N_MAX) N = N_MAX;

    // Zero row counters with a memset node (cheaper than a zeroing kernel).
    void* count_ptr = nullptr;
    cudaGetSymbolAddress(&count_ptr, g_count);        // address query — capture-safe
    cudaMemsetAsync(count_ptr, 0, (size_t)N * sizeof(int));

    int eg = (E + 255) / 256;
    scatter_bucket<<<eg, 256>>>(idx, vals, E);

    long long threads = (long long)N * 32;
    spmm_bucket<<<(unsigned)((threads + 255) / 256), 256>>>(b, out, N);
    apply_overflow<<<1, 256>>>(b, out);
}

// round 16
// speedup vs baseline: 1.0021x; 1.0021x over previous
#include <cuda_runtime.h>
#include <cstdint>

// COO SpMM via direct fixed-capacity row buckets, D = 64.
// R16: CAP 128 -> 64 so the bucket array (51MB addr space) stays L2-resident
//      together with b/out (total ~103MB < 126MB L2). Poisson(32) tail:
//      P(deg>64) ~ 3e-7 -> ~0.03 expected overflow edges (ovf path covers).
//      Bucket stores use evict-first hint (write-once read-once data).
//      Hot-loop code is frozen at the proven R10/R15 form.

#define D_DIM    64
#define N_MAX    100000
#define E_MAX    3200000
#define CAP      64           // slots per row (avg degree 32)
#define OVF_CAP  8192

__device__ int  g_count[N_MAX];                  // memset per launch
__device__ int2 g_bucket[(size_t)N_MAX * CAP];   // {col, float bits of val}
__device__ int  g_ovf_count;                     // zero-init; self-reset by ovf kernel
__device__ int4 g_ovf[OVF_CAP];                  // {row, col, valbits, 0}

// ---- Phase 1: bucket scatter ----------------------------------------------------

__global__ void scatter_bucket(const int* __restrict__ idx,
                               const float* __restrict__ vals, int E) {
    int e = blockIdx.x * blockDim.x + threadIdx.x;
    if (e >= E) return;
    int row = idx[e];
    int col = idx[E + e];
    int vb  = __float_as_int(vals[e]);
    int pos = atomicAdd(&g_count[row], 1);
    if (pos < CAP) {
        // evict-first store: written once here, read once by spmm
        int2* dst = &g_bucket[(size_t)row * CAP + pos];
        asm volatile("st.global.cs.v2.s32 [%0], {%1, %2};"
                     :: "l"(dst), "r"(col), "r"(vb) : "memory");
    } else {
        int o = atomicAdd(&g_ovf_count, 1);
        if (o < OVF_CAP) g_ovf[o] = make_int4(row, col, vb, 0);
    }
}

// ---- Phase 2: one warp per row; int4 bucket loads (exact R10 body) --------------

__global__ void __launch_bounds__(256) spmm_bucket(const float* __restrict__ b,
                                                   float* __restrict__ out, int n) {
    int warp = (blockIdx.x * blockDim.x + threadIdx.x) >> 5;
    int lane = threadIdx.x & 31;
    if (warp >= n) return;

    int cnt = g_count[warp];
    if (cnt > CAP) cnt = CAP;

    const int4* __restrict__ bkt4 =
        reinterpret_cast<const int4*>(g_bucket + (size_t)warp * CAP);
    const float2* __restrict__ B = reinterpret_cast<const float2*>(b);
    float a0 = 0.f, a1 = 0.f;

    int pairs = cnt >> 1;
    #pragma unroll 2
    for (int i = 0; i < pairs; i++) {
        int4  p  = bkt4[i];                   // 2 edges in one broadcast LDG
        float v0 = __int_as_float(p.y);
        float v1 = __int_as_float(p.w);
        float2 b0 = __ldg(&B[(long long)p.x * 32 + lane]);
        float2 b1 = __ldg(&B[(long long)p.z * 32 + lane]);
        a0 = fmaf(v0, b0.x, a0);
        a1 = fmaf(v0, b0.y, a1);
        a0 = fmaf(v1, b1.x, a0);
        a1 = fmaf(v1, b1.y, a1);
    }
    if (cnt & 1) {
        int2  p  = g_bucket[(size_t)warp * CAP + (cnt - 1)];
        float v  = __int_as_float(p.y);
        float2 bv = __ldg(&B[(long long)p.x * 32 + lane]);
        a0 = fmaf(v, bv.x, a0);
        a1 = fmaf(v, bv.y, a1);
    }

    reinterpret_cast<float2*>(out)[(long long)warp * 32 + lane] =
        make_float2(a0, a1);
}

// ---- Phase 3: overflow apply (1 block; normally instant exit) -------------------

__global__ void apply_overflow(const float* __restrict__ b,
                               float* __restrict__ out) {
    int novf = g_ovf_count;
    if (novf == 0) return;                 // the expected path
    if (novf > OVF_CAP) novf = OVF_CAP;

    int t = threadIdx.x;
    for (int s = t; s < novf * 16; s += blockDim.x) {
        int  k = s >> 4;
        int  j = (s & 15) << 2;
        int4 ov = g_ovf[k];
        float v = __int_as_float(ov.z);
        const float4 bv =
            *reinterpret_cast<const float4*>(b + (long long)ov.y * D_DIM + j);
        float* dst = out + (long long)ov.x * D_DIM + j;
        asm volatile("red.global.add.v4.f32 [%0], {%1, %2, %3, %4};"
                     :: "l"(dst), "f"(bv.x * v), "f"(bv.y * v),
                        "f"(bv.z * v), "f"(bv.w * v)
                     : "memory");
    }
    __syncthreads();
    if (t == 0) g_ovf_count = 0;           // self-reset for next replay
}

// ---- Launch ----------------------------------------------------------------------

extern "C" void kernel_launch(void* const* d_in, const int* in_sizes, int n_in,
                              void* d_out, int out_size) {
    const int*   idx  = (const int*)d_in[0];          // [2, E]
    const float* vals = (const float*)d_in[1];        // [E]
    const float* b    = (const float*)d_in[n_in - 1]; // [N, 64]
    float*       out  = (float*)d_out;

    int E = in_sizes[1];
    int N = out_size / D_DIM;
    if (E > E_MAX) E = E_MAX;
    if (N > N_MAX) N = N_MAX;

    void* count_ptr = nullptr;
    cudaGetSymbolAddress(&count_ptr, g_count);        // address query — capture-safe
    cudaMemsetAsync(count_ptr, 0, (size_t)N * sizeof(int));

    int eg = (E + 255) / 256;
    scatter_bucket<<<eg, 256>>>(idx, vals, E);

    long long threads = (long long)N * 32;
    spmm_bucket<<<(unsigned)((threads + 255) / 256), 256>>>(b, out, N);
    apply_overflow<<<1, 256>>>(b, out);
}